// round 10
// baseline (speedup 1.0000x reference)
#include <cuda_runtime.h>
#include <cuda_bf16.h>
#include <math.h>
#include <float.h>

#define NN   50000
#define DD   128
#define NE   800000
#define TOTF (NN * DD)          // 6,400,000
#define NSLOT 32
#define CSRB  148               // persistent CSR blocks (co-resident)
#define CHUNK 338               // ceil(NN/CSRB)

#define GEMM_SMEM  ((2*128*36 + 2*32*132) * 4)   // 70656 bytes

// ---------------- scratch (static device globals only) ----------------
__device__ uint4  g_xwb4[TOTF / 8];
__device__ uint4  g_xlb4[TOTF / 8];
__device__ uint4  g_h1b4[TOTF / 8];
__device__ uint4  g_h2b4[TOTF / 8];
__device__ uint4  g_xrb4[TOTF / 8];
__device__ float  g_dinv[NN];
__device__ int    g_cnt[NN];
__device__ int    g_ptr[NN + 1];
__device__ int    g_ptr2[NN];
__device__ int    g_csr_src[NE];
__device__ int    g_bsum[CSRB];
__device__ int    g_arrive;
__device__ double g_stats[4][NSLOT * 2];

// ---------------- helpers ----------------
__device__ __forceinline__ float lrelu(float x) { return x > 0.f ? x : 0.2f * x; }

__device__ __forceinline__ unsigned f2tf(float x) {
    unsigned u; asm("cvt.rna.tf32.f32 %0, %1;" : "=r"(u) : "f"(x)); return u;
}

__device__ __forceinline__ unsigned pack_bf2(float a, float b) {
    __nv_bfloat162 h = __floats2bfloat162_rn(a, b);
    return *(unsigned*)&h;
}

__device__ __forceinline__ float4 bf4_to_f4(unsigned lo, unsigned hi) {
    __nv_bfloat162 a = *(__nv_bfloat162*)&lo;
    __nv_bfloat162 b = *(__nv_bfloat162*)&hi;
    return make_float4(__low2float(a), __high2float(a), __low2float(b), __high2float(b));
}

__device__ __forceinline__ void mma_tf32(float* d, const unsigned* a, const unsigned* b) {
    asm volatile("mma.sync.aligned.m16n8k8.row.col.f32.tf32.tf32.f32 "
                 "{%0,%1,%2,%3}, {%4,%5,%6,%7}, {%8,%9}, {%0,%1,%2,%3};"
                 : "+f"(d[0]), "+f"(d[1]), "+f"(d[2]), "+f"(d[3])
                 : "r"(a[0]), "r"(a[1]), "r"(a[2]), "r"(a[3]),
                   "r"(b[0]), "r"(b[1]));
}

__device__ __forceinline__ void stats_from_slots(const double* slot, float* mi) {
    double s = 0.0, sq = 0.0;
#pragma unroll
    for (int i = 0; i < NSLOT; i++) { s += slot[2 * i]; sq += slot[2 * i + 1]; }
    double m   = s / (double)TOTF;
    double var = sq / (double)TOTF - m * m;
    mi[0] = (float)m;
    mi[1] = 1.f / ((float)sqrt(fmax(var, 0.0)) + 1e-5f);
}

// ---------------- init ----------------
__global__ void init_zero_kernel() {
    int i = blockIdx.x * blockDim.x + threadIdx.x;
    if (i < NN) g_cnt[i] = 0;
    if (i < 4 * NSLOT * 2) ((double*)g_stats)[i] = 0.0;
    if (i == 0) g_arrive = 0;
}

// ---------------- persistent CSR build: hist + scan + scatter -----------------
__device__ __forceinline__ void grid_barrier(int target) {
    __syncthreads();
    if (threadIdx.x == 0) {
        __threadfence();
        atomicAdd(&g_arrive, 1);
        while (atomicAdd(&g_arrive, 0) < target) { }
    }
    __syncthreads();
}

__global__ __launch_bounds__(256)
void csr_build_kernel(const int* __restrict__ src, const int* __restrict__ dst)
{
    __shared__ int sh[256];
    int b = blockIdx.x, tid = threadIdx.x;

    // phase 1: histogram
    for (int e = b * 256 + tid; e < NE; e += CSRB * 256)
        atomicAdd(&g_cnt[dst[e]], 1);
    grid_barrier(CSRB);

    // phase 2: block-chunk totals
    int base = b * CHUNK;
    int lim  = min(base + CHUNK, NN);
    {
        int t = 0;
        for (int i = base + tid; i < lim; i += 256) t += __ldcg(&g_cnt[i]);
        sh[tid] = t;
        __syncthreads();
#pragma unroll
        for (int o = 128; o > 0; o >>= 1) {
            if (tid < o) sh[tid] += sh[tid + o];
            __syncthreads();
        }
        if (tid == 0) g_bsum[b] = sh[0];
    }
    grid_barrier(2 * CSRB);

    // phase 3: prefix + local exclusive scan
    int pre;
    {
        sh[tid] = (tid < b) ? __ldcg(&g_bsum[tid]) : 0;
        __syncthreads();
#pragma unroll
        for (int o = 128; o > 0; o >>= 1) {
            if (tid < o) sh[tid] += sh[tid + o];
            __syncthreads();
        }
        pre = sh[0];
        __syncthreads();
    }
    int carry = pre;
#pragma unroll
    for (int tile = 0; tile < 2; tile++) {
        int li = tile * 256 + tid;
        int i  = base + li;
        int ok = (li < CHUNK) && (i < NN);
        int v  = ok ? __ldcg(&g_cnt[i]) : 0;
        sh[tid] = v;
        __syncthreads();
#pragma unroll
        for (int off = 1; off < 256; off <<= 1) {
            int t = (tid >= off) ? sh[tid - off] : 0;
            __syncthreads();
            sh[tid] += t;
            __syncthreads();
        }
        int incl = sh[tid];
        if (ok) {
            int excl = carry + incl - v;
            g_ptr[i]  = excl;
            g_ptr2[i] = excl;
            g_dinv[i] = rsqrtf((float)(v + 1));
        }
        __syncthreads();
        carry += sh[255];
        __syncthreads();
    }
    if (b == 0 && tid == 0) g_ptr[NN] = NE;
    grid_barrier(3 * CSRB);

    // phase 4: scatter
    for (int e = b * 256 + tid; e < NE; e += CSRB * 256) {
        int pos = atomicAdd(&g_ptr2[dst[e]], 1);
        g_csr_src[pos] = src[e];
    }
}

// ---------------- TF32 GEMM N=128 (A fp32 or bf16): Cbf16 = rowscale*(nr(A)@W)
template <int ABF16>
__global__ __launch_bounds__(256, 2)
void gemm_tf32_kernel(const void* __restrict__ Avoid, const float* __restrict__ W,
                      unsigned* __restrict__ Cb, int M,
                      const float* __restrict__ gamma, const float* __restrict__ beta,
                      const double* __restrict__ slot, const float* __restrict__ rowscale)
{
    extern __shared__ unsigned smem_raw[];
    unsigned (*As)[128][36] = (unsigned (*)[128][36])smem_raw;
    unsigned (*Bs)[32][132] = (unsigned (*)[32][132])(smem_raw + 2 * 128 * 36);
    __shared__ float s_mi[2];
    const float* Af = (const float*)Avoid;
    const uint2* Ab = (const uint2*)Avoid;

    int tid  = threadIdx.x;
    int wid  = tid >> 5, lane = tid & 31;
    int wm   = wid & 3, wn = wid >> 2;
    int m0   = blockIdx.x * 128;

    if (tid == 0) {
        if (slot) stats_from_slots(slot, s_mi);
        else { s_mi[0] = 0.f; s_mi[1] = 1.f; }
    }
    __syncthreads();
    float mu = s_mi[0], inv = s_mi[1];
    bool donorm = (slot != nullptr);

    float acc[2][8][4];
#pragma unroll
    for (int i = 0; i < 2; i++)
#pragma unroll
        for (int j = 0; j < 8; j++)
#pragma unroll
            for (int q = 0; q < 4; q++) acc[i][j][q] = 0.f;

    int Ar[4], Aq[4], Br[4], Bq[4];
#pragma unroll
    for (int i = 0; i < 4; i++) {
        int lin = tid + i * 256;
        Ar[i] = lin >> 3;  Aq[i] = (lin & 7) * 4;
        Br[i] = lin >> 5;  Bq[i] = (lin & 31) * 4;
    }
    float4 ra[4], rb[4];

#define LOAD_TILE(k0)                                                              \
    {                                                                              \
        _Pragma("unroll")                                                          \
        for (int i = 0; i < 4; i++) {                                              \
            if (m0 + Ar[i] < M) {                                                  \
                if (ABF16) {                                                       \
                    uint2 u = Ab[(size_t)(m0 + Ar[i]) * 32 + (((k0) + Aq[i]) >> 2)];\
                    ra[i] = bf4_to_f4(u.x, u.y);                                   \
                } else                                                             \
                    ra[i] = *(const float4*)(Af + (size_t)(m0 + Ar[i]) * 128       \
                                             + (k0) + Aq[i]);                      \
            } else ra[i] = make_float4(0.f, 0.f, 0.f, 0.f);                        \
            rb[i] = *(const float4*)(W + (size_t)((k0) + Br[i]) * 128 + Bq[i]);    \
        }                                                                          \
    }
#define STORE_TILE(buf, k0)                                                        \
    {                                                                              \
        _Pragma("unroll")                                                          \
        for (int i = 0; i < 4; i++) {                                              \
            float4 v = ra[i];                                                      \
            if (donorm) {                                                          \
                float4 gv = *(const float4*)(gamma + (k0) + Aq[i]);                \
                float4 bv = *(const float4*)(beta  + (k0) + Aq[i]);                \
                v.x = fmaxf((v.x - mu) * inv * gv.x + bv.x, 0.f);                  \
                v.y = fmaxf((v.y - mu) * inv * gv.y + bv.y, 0.f);                  \
                v.z = fmaxf((v.z - mu) * inv * gv.z + bv.z, 0.f);                  \
                v.w = fmaxf((v.w - mu) * inv * gv.w + bv.w, 0.f);                  \
            }                                                                      \
            As[buf][Ar[i]][Aq[i] + 0] = f2tf(v.x);                                 \
            As[buf][Ar[i]][Aq[i] + 1] = f2tf(v.y);                                 \
            As[buf][Ar[i]][Aq[i] + 2] = f2tf(v.z);                                 \
            As[buf][Ar[i]][Aq[i] + 3] = f2tf(v.w);                                 \
            Bs[buf][Br[i]][Bq[i] + 0] = f2tf(rb[i].x);                             \
            Bs[buf][Br[i]][Bq[i] + 1] = f2tf(rb[i].y);                             \
            Bs[buf][Br[i]][Bq[i] + 2] = f2tf(rb[i].z);                             \
            Bs[buf][Br[i]][Bq[i] + 3] = f2tf(rb[i].w);                             \
        }                                                                          \
    }
#define COMPUTE(buf)                                                               \
    {                                                                              \
        _Pragma("unroll")                                                          \
        for (int kk = 0; kk < 32; kk += 8) {                                       \
            unsigned a[2][4], b[8][2];                                             \
            int ar = wm * 32 + (lane >> 2);                                        \
            int ak = kk + (lane & 3);                                              \
            a[0][0] = As[buf][ar][ak];          a[0][1] = As[buf][ar + 8][ak];     \
            a[0][2] = As[buf][ar][ak + 4];      a[0][3] = As[buf][ar + 8][ak + 4]; \
            a[1][0] = As[buf][ar + 16][ak];     a[1][1] = As[buf][ar + 24][ak];    \
            a[1][2] = As[buf][ar + 16][ak + 4]; a[1][3] = As[buf][ar + 24][ak + 4];\
            _Pragma("unroll")                                                      \
            for (int j = 0; j < 8; j++) {                                          \
                int col = wn * 64 + j * 8 + (lane >> 2);                           \
                b[j][0] = Bs[buf][kk + (lane & 3)][col];                           \
                b[j][1] = Bs[buf][kk + 4 + (lane & 3)][col];                       \
            }                                                                      \
            _Pragma("unroll")                                                      \
            for (int i = 0; i < 2; i++)                                            \
                _Pragma("unroll")                                                  \
                for (int j = 0; j < 8; j++) mma_tf32(acc[i][j], a[i], b[j]);       \
        }                                                                          \
    }

    LOAD_TILE(0);
    STORE_TILE(0, 0);
    __syncthreads();
#pragma unroll
    for (int t = 0; t < 4; t++) {
        if (t < 3) LOAD_TILE((t + 1) * 32);
        COMPUTE(t & 1);
        if (t < 3) { STORE_TILE((t + 1) & 1, (t + 1) * 32); __syncthreads(); }
    }

#pragma unroll
    for (int i = 0; i < 2; i++) {
#pragma unroll
        for (int j = 0; j < 8; j++) {
            int r0 = m0 + wm * 32 + i * 16 + (lane >> 2);
            int cc = wn * 64 + j * 8 + (lane & 3) * 2;
            if (r0 < M) {
                float sc = rowscale[r0];
                Cb[(size_t)r0 * 64 + (cc >> 1)] = pack_bf2(acc[i][j][0] * sc, acc[i][j][1] * sc);
            }
            if (r0 + 8 < M) {
                float sc = rowscale[r0 + 8];
                Cb[(size_t)(r0 + 8) * 64 + (cc >> 1)] = pack_bf2(acc[i][j][2] * sc, acc[i][j][3] * sc);
            }
        }
    }
#undef LOAD_TILE
#undef STORE_TILE
#undef COMPUTE
}

// ---------------- GAT GEMM: one launch, 2*GRID halves (xl | xr), A bf16 -------
__global__ __launch_bounds__(256, 2)
void gemm_gat2_kernel(const uint2* __restrict__ Ab,
                      const float* __restrict__ Wl, const float* __restrict__ bl,
                      const float* __restrict__ Wr, const float* __restrict__ br,
                      unsigned* __restrict__ XLb, unsigned* __restrict__ XRb,
                      int M, int gridHalf,
                      const float* __restrict__ gamma, const float* __restrict__ beta,
                      const double* __restrict__ slot)
{
    extern __shared__ unsigned smem_raw[];
    unsigned (*As)[128][36] = (unsigned (*)[128][36])smem_raw;
    unsigned (*Bs)[32][132] = (unsigned (*)[32][132])(smem_raw + 2 * 128 * 36);
    __shared__ float s_mi[2];

    int half = (blockIdx.x >= gridHalf) ? 1 : 0;
    const float* W   = half ? Wr : Wl;
    const float* bia = half ? br : bl;
    unsigned*    Cb  = half ? XRb : XLb;
    int m0 = (blockIdx.x - half * gridHalf) * 128;

    int tid  = threadIdx.x;
    int wid  = tid >> 5, lane = tid & 31;
    int wm   = wid & 3, wn = wid >> 2;

    if (tid == 0) stats_from_slots(slot, s_mi);
    __syncthreads();
    float mu = s_mi[0], inv = s_mi[1];

    float acc[2][8][4];
#pragma unroll
    for (int i = 0; i < 2; i++)
#pragma unroll
        for (int j = 0; j < 8; j++)
#pragma unroll
            for (int q = 0; q < 4; q++) acc[i][j][q] = 0.f;

    int Ar[4], Aq[4], Br_[4], Bq[4];
#pragma unroll
    for (int i = 0; i < 4; i++) {
        int lin = tid + i * 256;
        Ar[i]  = lin >> 3;  Aq[i] = (lin & 7) * 4;
        Br_[i] = lin >> 5;  Bq[i] = (lin & 31) * 4;
    }
    float4 ra[4], rb[4];

#define LOAD_TILE(k0)                                                              \
    {                                                                              \
        _Pragma("unroll")                                                          \
        for (int i = 0; i < 4; i++) {                                              \
            if (m0 + Ar[i] < M) {                                                  \
                uint2 u = Ab[(size_t)(m0 + Ar[i]) * 32 + (((k0) + Aq[i]) >> 2)];   \
                ra[i] = bf4_to_f4(u.x, u.y);                                       \
            } else ra[i] = make_float4(0.f, 0.f, 0.f, 0.f);                        \
            rb[i] = *(const float4*)(W + (size_t)((k0) + Br_[i]) * 128 + Bq[i]);   \
        }                                                                          \
    }
#define STORE_TILE(buf, k0)                                                        \
    {                                                                              \
        _Pragma("unroll")                                                          \
        for (int i = 0; i < 4; i++) {                                              \
            float4 v = ra[i];                                                      \
            float4 gv = *(const float4*)(gamma + (k0) + Aq[i]);                    \
            float4 bv = *(const float4*)(beta  + (k0) + Aq[i]);                    \
            v.x = fmaxf((v.x - mu) * inv * gv.x + bv.x, 0.f);                      \
            v.y = fmaxf((v.y - mu) * inv * gv.y + bv.y, 0.f);                      \
            v.z = fmaxf((v.z - mu) * inv * gv.z + bv.z, 0.f);                      \
            v.w = fmaxf((v.w - mu) * inv * gv.w + bv.w, 0.f);                      \
            As[buf][Ar[i]][Aq[i] + 0] = f2tf(v.x);                                 \
            As[buf][Ar[i]][Aq[i] + 1] = f2tf(v.y);                                 \
            As[buf][Ar[i]][Aq[i] + 2] = f2tf(v.z);                                 \
            As[buf][Ar[i]][Aq[i] + 3] = f2tf(v.w);                                 \
            Bs[buf][Br_[i]][Bq[i] + 0] = f2tf(rb[i].x);                            \
            Bs[buf][Br_[i]][Bq[i] + 1] = f2tf(rb[i].y);                            \
            Bs[buf][Br_[i]][Bq[i] + 2] = f2tf(rb[i].z);                            \
            Bs[buf][Br_[i]][Bq[i] + 3] = f2tf(rb[i].w);                            \
        }                                                                          \
    }
#define COMPUTE(buf)                                                               \
    {                                                                              \
        _Pragma("unroll")                                                          \
        for (int kk = 0; kk < 32; kk += 8) {                                       \
            unsigned a[2][4], b[8][2];                                             \
            int ar = wm * 32 + (lane >> 2);                                        \
            int ak = kk + (lane & 3);                                              \
            a[0][0] = As[buf][ar][ak];          a[0][1] = As[buf][ar + 8][ak];     \
            a[0][2] = As[buf][ar][ak + 4];      a[0][3] = As[buf][ar + 8][ak + 4]; \
            a[1][0] = As[buf][ar + 16][ak];     a[1][1] = As[buf][ar + 24][ak];    \
            a[1][2] = As[buf][ar + 16][ak + 4]; a[1][3] = As[buf][ar + 24][ak + 4];\
            _Pragma("unroll")                                                      \
            for (int j = 0; j < 8; j++) {                                          \
                int col = wn * 64 + j * 8 + (lane >> 2);                           \
                b[j][0] = Bs[buf][kk + (lane & 3)][col];                           \
                b[j][1] = Bs[buf][kk + 4 + (lane & 3)][col];                       \
            }                                                                      \
            _Pragma("unroll")                                                      \
            for (int i = 0; i < 2; i++)                                            \
                _Pragma("unroll")                                                  \
                for (int j = 0; j < 8; j++) mma_tf32(acc[i][j], a[i], b[j]);       \
        }                                                                          \
    }

    LOAD_TILE(0);
    STORE_TILE(0, 0);
    __syncthreads();
#pragma unroll
    for (int t = 0; t < 4; t++) {
        if (t < 3) LOAD_TILE((t + 1) * 32);
        COMPUTE(t & 1);
        if (t < 3) { STORE_TILE((t + 1) & 1, (t + 1) * 32); __syncthreads(); }
    }

#pragma unroll
    for (int i = 0; i < 2; i++) {
#pragma unroll
        for (int j = 0; j < 8; j++) {
            int r0 = m0 + wm * 32 + i * 16 + (lane >> 2);
            int cc = wn * 64 + j * 8 + (lane & 3) * 2;
            float b0 = bia[cc], b1 = bia[cc + 1];
            if (r0 < M)
                Cb[(size_t)r0 * 64 + (cc >> 1)] = pack_bf2(acc[i][j][0] + b0, acc[i][j][1] + b1);
            if (r0 + 8 < M)
                Cb[(size_t)(r0 + 8) * 64 + (cc >> 1)] = pack_bf2(acc[i][j][2] + b0, acc[i][j][3] + b1);
        }
    }
#undef LOAD_TILE
#undef STORE_TILE
#undef COMPUTE
}

// ---------------- block stat reduce (post-divergence, full warp) -------
__device__ __forceinline__ void accum_stats2(float s, float sq, int lane, int tid,
                                             double* slot)
{
#pragma unroll
    for (int off = 16; off > 0; off >>= 1) {
        s  += __shfl_xor_sync(0xffffffffu, s,  off);
        sq += __shfl_xor_sync(0xffffffffu, sq, off);
    }
    __shared__ float bs[2];
    if (tid == 0) { bs[0] = 0.f; bs[1] = 0.f; }
    __syncthreads();
    if (lane == 0) { atomicAdd(&bs[0], s); atomicAdd(&bs[1], sq); }
    __syncthreads();
    if (tid == 0) {
        int sl = blockIdx.x & (NSLOT - 1);
        atomicAdd(&slot[2 * sl],     (double)bs[0]);
        atomicAdd(&slot[2 * sl + 1], (double)bs[1]);
    }
}

// ---------------- GCN gather (half-warp/node, bf16 in, bf16 out) --------------
// No shuffles inside the divergent edge loop -> safe with half-warp nodes.
__global__ void gcn_gather_kernel(const float* __restrict__ bias,
                                  uint4* __restrict__ outb, double* __restrict__ slot)
{
    int tid  = threadIdx.x;
    int lane = tid & 31;
    int l16  = tid & 15;
    int n = (blockIdx.x * blockDim.x + tid) >> 4;   // grid exact
    int c = l16 * 8;

    uint4 u0 = g_xwb4[(size_t)n * 16 + l16];        // self (pre-scaled)
    float4 aL = bf4_to_f4(u0.x, u0.y);
    float4 aH = bf4_to_f4(u0.z, u0.w);

    int e = g_ptr[n], end = g_ptr[n + 1];
    for (; e + 3 < end; e += 4) {
        uint4 v0 = g_xwb4[(size_t)g_csr_src[e] * 16 + l16];
        uint4 v1 = g_xwb4[(size_t)g_csr_src[e + 1] * 16 + l16];
        uint4 v2 = g_xwb4[(size_t)g_csr_src[e + 2] * 16 + l16];
        uint4 v3 = g_xwb4[(size_t)g_csr_src[e + 3] * 16 + l16];
        float4 a0 = bf4_to_f4(v0.x, v0.y), b0 = bf4_to_f4(v0.z, v0.w);
        float4 a1 = bf4_to_f4(v1.x, v1.y), b1 = bf4_to_f4(v1.z, v1.w);
        float4 a2 = bf4_to_f4(v2.x, v2.y), b2 = bf4_to_f4(v2.z, v2.w);
        float4 a3 = bf4_to_f4(v3.x, v3.y), b3 = bf4_to_f4(v3.z, v3.w);
        aL.x += (a0.x + a1.x) + (a2.x + a3.x);
        aL.y += (a0.y + a1.y) + (a2.y + a3.y);
        aL.z += (a0.z + a1.z) + (a2.z + a3.z);
        aL.w += (a0.w + a1.w) + (a2.w + a3.w);
        aH.x += (b0.x + b1.x) + (b2.x + b3.x);
        aH.y += (b0.y + b1.y) + (b2.y + b3.y);
        aH.z += (b0.z + b1.z) + (b2.z + b3.z);
        aH.w += (b0.w + b1.w) + (b2.w + b3.w);
    }
    for (; e < end; e++) {
        uint4 v = g_xwb4[(size_t)g_csr_src[e] * 16 + l16];
        float4 a = bf4_to_f4(v.x, v.y), b = bf4_to_f4(v.z, v.w);
        aL.x += a.x; aL.y += a.y; aL.z += a.z; aL.w += a.w;
        aH.x += b.x; aH.y += b.y; aH.z += b.z; aH.w += b.w;
    }
    float dn = g_dinv[n];
    float4 bL = *(const float4*)(bias + c);
    float4 bH = *(const float4*)(bias + c + 4);
    aL.x = aL.x * dn + bL.x; aL.y = aL.y * dn + bL.y;
    aL.z = aL.z * dn + bL.z; aL.w = aL.w * dn + bL.w;
    aH.x = aH.x * dn + bH.x; aH.y = aH.y * dn + bH.y;
    aH.z = aH.z * dn + bH.z; aH.w = aH.w * dn + bH.w;
    outb[(size_t)n * 16 + l16] = make_uint4(pack_bf2(aL.x, aL.y), pack_bf2(aL.z, aL.w),
                                            pack_bf2(aH.x, aH.y), pack_bf2(aH.z, aH.w));
    float s  = (aL.x + aL.y + aL.z + aL.w) + (aH.x + aH.y + aH.z + aH.w);
    float sq = aL.x*aL.x + aL.y*aL.y + aL.z*aL.z + aL.w*aL.w
             + aH.x*aH.x + aH.y*aH.y + aH.z*aH.z + aH.w*aH.w;
    accum_stats2(s, sq, lane, tid, slot);
}

// ---------------- fused GATv2 gather (half-warp/node) -------------------------
// All in-loop shuffles use the HALF-WARP member mask: the two half-warps run
// divergent trip counts (different nodes), full-warp masks would deadlock.
template <int H, int OUTF32>
__global__ void gat_gather_kernel(const float* __restrict__ att, const float* __restrict__ bg,
                                  float* __restrict__ outf, uint4* __restrict__ outb,
                                  double* __restrict__ slot)
{
    int tid  = threadIdx.x;
    int lane = tid & 31;
    int l16  = tid & 15;
    unsigned hm = (lane & 16) ? 0xFFFF0000u : 0x0000FFFFu;   // half-warp mask
    int n = (blockIdx.x * blockDim.x + tid) >> 4;
    int c = l16 * 8;

    uint4 ur = g_xrb4[(size_t)n * 16 + l16];
    float4 xrL = bf4_to_f4(ur.x, ur.y);
    float4 xrH = bf4_to_f4(ur.z, ur.w);
    float4 wL = *(const float4*)(att + c);
    float4 wH = *(const float4*)(att + c + 4);

    float m = -FLT_MAX, ssum = 0.f;
    float4 acL = make_float4(0.f, 0.f, 0.f, 0.f);
    float4 acH = make_float4(0.f, 0.f, 0.f, 0.f);

    const int LPH = 16 / H;   // lanes per head within half-warp

#define GAT_SCORE(a, b, p)                                                         \
    p = wL.x * lrelu((a).x + xrL.x) + wL.y * lrelu((a).y + xrL.y)                  \
      + wL.z * lrelu((a).z + xrL.z) + wL.w * lrelu((a).w + xrL.w)                  \
      + wH.x * lrelu((b).x + xrH.x) + wH.y * lrelu((b).y + xrH.y)                  \
      + wH.z * lrelu((b).z + xrH.z) + wH.w * lrelu((b).w + xrH.w);

#define GAT_PROC1(a, b)                                                            \
    {                                                                              \
        float p; GAT_SCORE(a, b, p);                                               \
        _Pragma("unroll")                                                          \
        for (int off = 1; off < LPH; off <<= 1)                                    \
            p += __shfl_xor_sync(hm, p, off);                                      \
        float mn = fmaxf(m, p);                                                    \
        float sc = __expf(m - mn);                                                 \
        float wg = __expf(p - mn);                                                 \
        ssum = ssum * sc + wg;                                                     \
        acL.x = acL.x * sc + wg * (a).x;  acL.y = acL.y * sc + wg * (a).y;         \
        acL.z = acL.z * sc + wg * (a).z;  acL.w = acL.w * sc + wg * (a).w;         \
        acH.x = acH.x * sc + wg * (b).x;  acH.y = acH.y * sc + wg * (b).y;         \
        acH.z = acH.z * sc + wg * (b).z;  acH.w = acH.w * sc + wg * (b).w;         \
        m = mn;                                                                    \
    }

    {   // self loop
        uint4 u = g_xlb4[(size_t)n * 16 + l16];
        float4 a = bf4_to_f4(u.x, u.y), b = bf4_to_f4(u.z, u.w);
        GAT_PROC1(a, b);
    }
    int e = g_ptr[n], end = g_ptr[n + 1];
    for (; e + 3 < end; e += 4) {
        uint4 u0 = g_xlb4[(size_t)g_csr_src[e] * 16 + l16];
        uint4 u1 = g_xlb4[(size_t)g_csr_src[e + 1] * 16 + l16];
        uint4 u2 = g_xlb4[(size_t)g_csr_src[e + 2] * 16 + l16];
        uint4 u3 = g_xlb4[(size_t)g_csr_src[e + 3] * 16 + l16];
        float4 a0 = bf4_to_f4(u0.x, u0.y), b0 = bf4_to_f4(u0.z, u0.w);
        float4 a1 = bf4_to_f4(u1.x, u1.y), b1 = bf4_to_f4(u1.z, u1.w);
        float4 a2 = bf4_to_f4(u2.x, u2.y), b2 = bf4_to_f4(u2.z, u2.w);
        float4 a3 = bf4_to_f4(u3.x, u3.y), b3 = bf4_to_f4(u3.z, u3.w);
        float p0, p1, p2, p3;
        GAT_SCORE(a0, b0, p0); GAT_SCORE(a1, b1, p1);
        GAT_SCORE(a2, b2, p2); GAT_SCORE(a3, b3, p3);
#pragma unroll
        for (int off = 1; off < LPH; off <<= 1) {
            p0 += __shfl_xor_sync(hm, p0, off);
            p1 += __shfl_xor_sync(hm, p1, off);
            p2 += __shfl_xor_sync(hm, p2, off);
            p3 += __shfl_xor_sync(hm, p3, off);
        }
        float bm = fmaxf(fmaxf(p0, p1), fmaxf(p2, p3));
        float mn = fmaxf(m, bm);
        float sc = __expf(m - mn);
        float w0 = __expf(p0 - mn), w1 = __expf(p1 - mn);
        float w2 = __expf(p2 - mn), w3 = __expf(p3 - mn);
        ssum = ssum * sc + ((w0 + w1) + (w2 + w3));
        acL.x = acL.x * sc + (w0 * a0.x + w1 * a1.x) + (w2 * a2.x + w3 * a3.x);
        acL.y = acL.y * sc + (w0 * a0.y + w1 * a1.y) + (w2 * a2.y + w3 * a3.y);
        acL.z = acL.z * sc + (w0 * a0.z + w1 * a1.z) + (w2 * a2.z + w3 * a3.z);
        acL.w = acL.w * sc + (w0 * a0.w + w1 * a1.w) + (w2 * a2.w + w3 * a3.w);
        acH.x = acH.x * sc + (w0 * b0.x + w1 * b1.x) + (w2 * b2.x + w3 * b3.x);
        acH.y = acH.y * sc + (w0 * b0.y + w1 * b1.y) + (w2 * b2.y + w3 * b3.y);
        acH.z = acH.z * sc + (w0 * b0.z + w1 * b1.z) + (w2 * b2.z + w3 * b3.z);
        acH.w = acH.w * sc + (w0 * b0.w + w1 * b1.w) + (w2 * b2.w + w3 * b3.w);
        m = mn;
    }
    for (; e < end; e++) {
        uint4 u = g_xlb4[(size_t)g_csr_src[e] * 16 + l16];
        float4 a = bf4_to_f4(u.x, u.y), b = bf4_to_f4(u.z, u.w);
        GAT_PROC1(a, b);
    }
#undef GAT_PROC1
#undef GAT_SCORE

    float inv = 1.f / ssum;
    float4 bL = *(const float4*)(bg + c);
    float4 bH = *(const float4*)(bg + c + 4);
    float4 oL, oH;
    oL.x = acL.x * inv + bL.x; oL.y = acL.y * inv + bL.y;
    oL.z = acL.z * inv + bL.z; oL.w = acL.w * inv + bL.w;
    oH.x = acH.x * inv + bH.x; oH.y = acH.y * inv + bH.y;
    oH.z = acH.z * inv + bH.z; oH.w = acH.w * inv + bH.w;
    if (OUTF32) {
        *(float4*)(outf + (size_t)n * 128 + c)     = oL;
        *(float4*)(outf + (size_t)n * 128 + c + 4) = oH;
    } else {
        outb[(size_t)n * 16 + l16] = make_uint4(pack_bf2(oL.x, oL.y), pack_bf2(oL.z, oL.w),
                                                pack_bf2(oH.x, oH.y), pack_bf2(oH.z, oH.w));
    }
    float s  = (oL.x + oL.y + oL.z + oL.w) + (oH.x + oH.y + oH.z + oH.w);
    float sq = oL.x*oL.x + oL.y*oL.y + oL.z*oL.z + oL.w*oL.w
             + oH.x*oH.x + oH.y*oH.y + oH.z*oH.z + oH.w*oH.w;
    accum_stats2(s, sq, lane, tid, slot);
}

// ---------------- final LayerNorm ----------------
__global__ void ln_final_kernel(float* __restrict__ x, const float* __restrict__ g,
                                const float* __restrict__ b, const double* __restrict__ slot)
{
    __shared__ float s_mi[2];
    if (threadIdx.x == 0) stats_from_slots(slot, s_mi);
    __syncthreads();
    float mu = s_mi[0], inv = s_mi[1];
    int i = (blockIdx.x * blockDim.x + threadIdx.x) * 4;
    int c = i & 127;
    float4 v  = *(const float4*)(x + i);
    float4 gv = *(const float4*)(g + c);
    float4 bv = *(const float4*)(b + c);
    v.x = (v.x - mu) * inv * gv.x + bv.x;
    v.y = (v.y - mu) * inv * gv.y + bv.y;
    v.z = (v.z - mu) * inv * gv.z + bv.z;
    v.w = (v.w - mu) * inv * gv.w + bv.w;
    *(float4*)(x + i) = v;
}

// ---------------- host orchestration ----------------
extern "C" void kernel_launch(void* const* d_in, const int* in_sizes, int n_in,
                              void* d_out, int out_size)
{
    const float* x    = (const float*)d_in[0];
    const int*   ei   = (const int*)  d_in[1];
    const float* W0   = (const float*)d_in[2];
    const float* b0   = (const float*)d_in[3];
    const float* g0   = (const float*)d_in[4];
    const float* be0  = (const float*)d_in[5];
    const float* Wl1  = (const float*)d_in[6];
    const float* bl1  = (const float*)d_in[7];
    const float* Wr1  = (const float*)d_in[8];
    const float* br1  = (const float*)d_in[9];
    const float* att1 = (const float*)d_in[10];
    const float* bg1  = (const float*)d_in[11];
    const float* g1   = (const float*)d_in[12];
    const float* be1  = (const float*)d_in[13];
    const float* W2   = (const float*)d_in[14];
    const float* b2   = (const float*)d_in[15];
    const float* g2   = (const float*)d_in[16];
    const float* be2  = (const float*)d_in[17];
    const float* Wl3  = (const float*)d_in[18];
    const float* bl3  = (const float*)d_in[19];
    const float* Wr3  = (const float*)d_in[20];
    const float* br3  = (const float*)d_in[21];
    const float* att3 = (const float*)d_in[22];
    const float* bg3  = (const float*)d_in[23];
    const float* g3   = (const float*)d_in[24];
    const float* be3  = (const float*)d_in[25];

    const int* src = ei;
    const int* dst = ei + NE;
    float* out = (float*)d_out;

    float* dinv;
    uint4 *xwb, *xlb, *h1b, *h2b, *xrb;
    double* st;
    cudaGetSymbolAddress((void**)&xwb, g_xwb4);
    cudaGetSymbolAddress((void**)&xlb, g_xlb4);
    cudaGetSymbolAddress((void**)&h1b, g_h1b4);
    cudaGetSymbolAddress((void**)&h2b, g_h2b4);
    cudaGetSymbolAddress((void**)&xrb, g_xrb4);
    cudaGetSymbolAddress((void**)&dinv, g_dinv);
    cudaGetSymbolAddress((void**)&st, g_stats);
    double* s0 = st;
    double* s1 = st + NSLOT * 2;
    double* s2 = st + NSLOT * 4;
    double* s3 = st + NSLOT * 6;

    cudaFuncSetAttribute(gemm_tf32_kernel<0>,
                         cudaFuncAttributeMaxDynamicSharedMemorySize, GEMM_SMEM);
    cudaFuncSetAttribute(gemm_tf32_kernel<1>,
                         cudaFuncAttributeMaxDynamicSharedMemorySize, GEMM_SMEM);
    cudaFuncSetAttribute(gemm_gat2_kernel,
                         cudaFuncAttributeMaxDynamicSharedMemorySize, GEMM_SMEM);

    const int GEMM_GRID = (NN + 127) / 128;       // 391
    const int HW_GRID   = NN * 16 / 256;          // 3125, exact

    // --- init + persistent CSR build ---
    init_zero_kernel<<<(NN + 255) / 256, 256>>>();
    csr_build_kernel<<<CSRB, 256>>>(src, dst);

    // layer 0: GCN (x fp32), xw bf16 pre-scaled by dinv -> h1 bf16, stats s0
    gemm_tf32_kernel<0><<<GEMM_GRID, 256, GEMM_SMEM>>>(x, W0, (unsigned*)xwb, NN,
                                                       nullptr, nullptr, nullptr, dinv);
    gcn_gather_kernel<<<HW_GRID, 256>>>(b0, h1b, s0);

    // layer 1: GATv2 H=8 (norm s0 + relu), xl/xr bf16 -> h2 bf16, stats s1
    gemm_gat2_kernel<<<2 * GEMM_GRID, 256, GEMM_SMEM>>>((const uint2*)h1b, Wl1, bl1, Wr1, br1,
                                                        (unsigned*)xlb, (unsigned*)xrb,
                                                        NN, GEMM_GRID, g0, be0, s0);
    gat_gather_kernel<8, 0><<<HW_GRID, 256>>>(att1, bg1, nullptr, h2b, s1);

    // layer 2: GCN (norm s1 + relu, A bf16) -> h1 bf16, stats s2
    gemm_tf32_kernel<1><<<GEMM_GRID, 256, GEMM_SMEM>>>(h2b, W2, (unsigned*)xwb, NN,
                                                       g1, be1, s1, dinv);
    gcn_gather_kernel<<<HW_GRID, 256>>>(b2, h1b, s2);

    // layer 3: GATv2 H=1 (norm s2 + relu, A bf16) -> out fp32, stats s3 -> final LN
    gemm_gat2_kernel<<<2 * GEMM_GRID, 256, GEMM_SMEM>>>((const uint2*)h1b, Wl3, bl3, Wr3, br3,
                                                        (unsigned*)xlb, (unsigned*)xrb,
                                                        NN, GEMM_GRID, g2, be2, s2);
    gat_gather_kernel<1, 1><<<HW_GRID, 256>>>(att3, bg3, out, nullptr, s3);
    ln_final_kernel<<<TOTF / 1024, 256>>>(out, g3, be3, s3);
}